// round 8
// baseline (speedup 1.0000x reference)
#include <cuda_runtime.h>

// ---------------- problem constants ----------------
#define B_ 16
#define N_ 512
#define H_ 512
#define G_ 8
#define L_ 16
#define D_ 64
#define SCALE_ 0.04419417382415922f   // 512^-0.5

// ---------------- device scratch (static: no allocs allowed) ----------------
__device__ float g_Q[B_*G_*N_*D_];          // (b,g,n,d)  16 MB
__device__ float g_K[B_*G_*N_*D_];          // (b,g,m,d)  16 MB
__device__ float g_V[B_*L_*N_*D_];          // (b,l,m,d)  32 MB
__device__ float g_S[B_*G_*N_*N_];          // (b,g,n,m) 128 MB
__device__ float g_A[B_*L_*N_*N_];          // (b,l,n,m) 256 MB
__device__ float g_O[B_*N_*L_*D_];          // (b,n,l,d)  32 MB

// ---------------- f32x2 helpers (FFMA2 only reachable via PTX) --------------
__device__ __forceinline__ unsigned long long pk2(float v) {
    unsigned long long r;
    asm("mov.b64 %0, {%1, %1};" : "=l"(r) : "f"(v));
    return r;
}
__device__ __forceinline__ void ffma2(unsigned long long& d,
                                      unsigned long long a,
                                      unsigned long long b) {
    asm("fma.rn.f32x2 %0, %1, %2, %0;" : "+l"(d) : "l"(a), "l"(b));
}
__device__ __forceinline__ float2 up2(unsigned long long v) {
    float2 f;
    asm("mov.b64 {%0, %1}, %2;" : "=f"(f.x), "=f"(f.y) : "l"(v));
    return f;
}

// mish(x) = x * tanh(softplus(x)) = x * (t^2+2t)/(t^2+2t+2), t = e^x
__device__ __forceinline__ float mishf(float x) {
    float t = __expf(fminf(x, 15.f));   // clamp: for x>15 ratio == 1 to fp32
    float u = t * t + 2.f * t;
    return x * __fdividef(u, u + 2.f);
}

// =============================================================================
// K1: QKV projection.  C(8192 x 2048) = X(8192x512) @ [Wq|Wk|Wv], scatter into
// g_Q (b,g,n,d), g_K (b,g,m,d), g_V (b,l,m,d) (+bv).
// Tile 128x128x16, 256 thr, 8x8/thread, f32x2 accumulators over row pairs.
// =============================================================================
__global__ void __launch_bounds__(256)
k1_proj(const float* __restrict__ x,  const float* __restrict__ Wq,
        const float* __restrict__ Wk, const float* __restrict__ Wv,
        const float* __restrict__ bv)
{
    __shared__ __align__(16) float As[16][130];  // transposed, pad 130 -> conflict-free
    __shared__ __align__(16) float Bs[16][128];

    const int tid = threadIdx.x;
    const int colTile = blockIdx.x;   // 0..15 (16 * 128 = 2048 cols)
    const int rowTile = blockIdx.y;   // 0..63

    const float* Wsrc; int colBase, mode, ldw;
    if (colTile < 4)      { Wsrc = Wq; colBase = colTile * 128;       mode = 0; ldw = 512;  }
    else if (colTile < 8) { Wsrc = Wk; colBase = (colTile - 4) * 128; mode = 1; ldw = 512;  }
    else                  { Wsrc = Wv; colBase = (colTile - 8) * 128; mode = 2; ldw = 1024; }

    const float* Ag = x + (size_t)rowTile * 128 * 512;

    const int ti = tid >> 4, tj = tid & 15;
    const int i0 = ti * 8, j0 = tj * 8;
    const int akk = tid & 15, arb = tid >> 4;

    unsigned long long c2[4][8];
#pragma unroll
    for (int p = 0; p < 4; p++)
#pragma unroll
        for (int j = 0; j < 8; j++) c2[p][j] = 0ull;

    for (int k0 = 0; k0 < 512; k0 += 16) {
#pragma unroll
        for (int it = 0; it < 8; it++) {
            int r = arb + 16 * it;
            As[akk][r] = Ag[(size_t)r * 512 + k0 + akk];
        }
#pragma unroll
        for (int it = 0; it < 2; it++) {
            int li = tid + 256 * it;
            int bkk = li >> 5, bjc = li & 31;
            *(float4*)&Bs[bkk][bjc * 4] =
                *(const float4*)&Wsrc[(size_t)(k0 + bkk) * ldw + colBase + bjc * 4];
        }
        __syncthreads();
#pragma unroll
        for (int kk = 0; kk < 16; kk++) {
            unsigned long long a2[4];
#pragma unroll
            for (int p = 0; p < 4; p++)
                a2[p] = *(const unsigned long long*)&As[kk][i0 + 2 * p];
            float4 b0 = *(const float4*)&Bs[kk][j0];
            float4 b1 = *(const float4*)&Bs[kk][j0 + 4];
            unsigned long long bb[8] = { pk2(b0.x), pk2(b0.y), pk2(b0.z), pk2(b0.w),
                                         pk2(b1.x), pk2(b1.y), pk2(b1.z), pk2(b1.w) };
#pragma unroll
            for (int p = 0; p < 4; p++)
#pragma unroll
                for (int j = 0; j < 8; j++) ffma2(c2[p][j], a2[p], bb[j]);
        }
        __syncthreads();
    }

    const int c = colBase + j0;            // 8 consecutive cols, same head (c%64 multiple of 8)
#pragma unroll
    for (int p = 0; p < 4; p++) {
        float2 rows[8];
#pragma unroll
        for (int j = 0; j < 8; j++) rows[j] = up2(c2[p][j]);
#pragma unroll
        for (int h = 0; h < 2; h++) {
            int i = i0 + 2 * p + h;
            int r = rowTile * 128 + i;
            int b = r >> 9, n = r & 511;
            float v[8];
#pragma unroll
            for (int j = 0; j < 8; j++) v[j] = h ? rows[j].y : rows[j].x;
            if (mode == 2) {
#pragma unroll
                for (int j = 0; j < 8; j++) v[j] += bv[c + j];
                int l = c >> 6, d = c & 63;
                float* dst = &g_V[(((b * 16 + l) * 512 + n) * 64) + d];
                *(float4*)dst       = make_float4(v[0], v[1], v[2], v[3]);
                *(float4*)(dst + 4) = make_float4(v[4], v[5], v[6], v[7]);
            } else {
                int g = c >> 6, d = c & 63;
                float* base = (mode == 0) ? g_Q : g_K;
                float* dst = base + (((b * 8 + g) * 512 + n) * 64) + d;
                *(float4*)dst       = make_float4(v[0], v[1], v[2], v[3]);
                *(float4*)(dst + 4) = make_float4(v[4], v[5], v[6], v[7]);
            }
        }
    }
}

// =============================================================================
// K2: scores. For each z=(b,g): S_z(512x512) = Q_z(512x64) @ K_z(512x64)^T.
// NT GEMM: both operands transpose-loaded into smem (pad 130).
// =============================================================================
__global__ void __launch_bounds__(256)
k2_scores()
{
    __shared__ __align__(16) float As[16][130];
    __shared__ __align__(16) float Bs[16][130];

    const int tid = threadIdx.x;
    const int z = blockIdx.z;                         // b*8+g
    const float* Qg = g_Q + (size_t)z * 512 * 64;
    const float* Kg = g_K + (size_t)z * 512 * 64;
    const int rowTile = blockIdx.y, colTile = blockIdx.x;   // each 0..3

    const int ti = tid >> 4, tj = tid & 15;
    const int i0 = ti * 8, j0 = tj * 8;
    const int lkk = tid & 15, lrb = tid >> 4;

    unsigned long long c2[4][8];
#pragma unroll
    for (int p = 0; p < 4; p++)
#pragma unroll
        for (int j = 0; j < 8; j++) c2[p][j] = 0ull;

    for (int k0 = 0; k0 < 64; k0 += 16) {
#pragma unroll
        for (int it = 0; it < 8; it++) {
            int r = lrb + 16 * it;
            As[lkk][r] = Qg[(size_t)(rowTile * 128 + r) * 64 + k0 + lkk];
            Bs[lkk][r] = Kg[(size_t)(colTile * 128 + r) * 64 + k0 + lkk];
        }
        __syncthreads();
#pragma unroll
        for (int kk = 0; kk < 16; kk++) {
            unsigned long long a2[4];
#pragma unroll
            for (int p = 0; p < 4; p++)
                a2[p] = *(const unsigned long long*)&As[kk][i0 + 2 * p];
            unsigned long long bb[8];
#pragma unroll
            for (int q = 0; q < 4; q++) {
                float2 bq = *(const float2*)&Bs[kk][j0 + 2 * q];
                bb[2 * q]     = pk2(bq.x);
                bb[2 * q + 1] = pk2(bq.y);
            }
#pragma unroll
            for (int p = 0; p < 4; p++)
#pragma unroll
                for (int j = 0; j < 8; j++) ffma2(c2[p][j], a2[p], bb[j]);
        }
        __syncthreads();
    }

    float* Sb = g_S + (size_t)z * 512 * 512;
#pragma unroll
    for (int p = 0; p < 4; p++) {
        float2 rows[8];
#pragma unroll
        for (int j = 0; j < 8; j++) rows[j] = up2(c2[p][j]);
#pragma unroll
        for (int h = 0; h < 2; h++) {
            int n = rowTile * 128 + i0 + 2 * p + h;
            float v[8];
#pragma unroll
            for (int j = 0; j < 8; j++) v[j] = h ? rows[j].y : rows[j].x;
            float* dst = Sb + (size_t)n * 512 + colTile * 128 + j0;
            *(float4*)dst       = make_float4(v[0], v[1], v[2], v[3]);
            *(float4*)(dst + 4) = make_float4(v[4], v[5], v[6], v[7]);
        }
    }
}

// =============================================================================
// K3: pointwise head-mix. a8 = S + sigma^2*eps; a16 = mish(a8@Wp1+bp1)@Wp2+bp2;
// a16 = a16*SCALE + prior(b,l,n,m); softmax over l (16); write A (b,l,n,m).
// 2 points per thread (m and m+256) to amortize weight LDS.
// =============================================================================
__global__ void __launch_bounds__(256)
k3_mix(const float* __restrict__ eps,  const float* __restrict__ prior,
       const float* __restrict__ sigma, const float* __restrict__ Wp1,
       const float* __restrict__ bp1,   const float* __restrict__ Wp2,
       const float* __restrict__ bp2)
{
    __shared__ float W1s[128];
    __shared__ float W2s[256];
    __shared__ float b1s[16], b2s[16], sg2[8];

    const int tid = threadIdx.x;
    if (tid < 128) W1s[tid] = Wp1[tid];
    W2s[tid] = Wp2[tid];
    if (tid < 16) { b1s[tid] = bp1[tid]; b2s[tid] = bp2[tid]; }
    if (tid < 8)  { float s = sigma[tid]; sg2[tid] = s * s; }
    __syncthreads();

    const int gidx = blockIdx.x * 256 + tid;   // grid 8192 -> 2.097M threads
    const int m = gidx & 255;
    const int n = (gidx >> 8) & 511;
    const int b = gidx >> 17;

    const size_t p0 = ((size_t)(b * 512 + n)) * 512 + m;   // (b,n,m) flat

    float t0[8], t1[8];
    {
        float e0[8], e1[8];
        const float4* ep0 = (const float4*)(eps + p0 * 8);
        const float4* ep1 = (const float4*)(eps + (p0 + 256) * 8);
        *(float4*)&e0[0] = ep0[0]; *(float4*)&e0[4] = ep0[1];
        *(float4*)&e1[0] = ep1[0]; *(float4*)&e1[4] = ep1[1];
#pragma unroll
        for (int g = 0; g < 8; g++) {
            size_t si = ((size_t)(b * 8 + g) * 512 + n) * 512 + m;
            t0[g] = g_S[si]       + sg2[g] * e0[g];
            t1[g] = g_S[si + 256] + sg2[g] * e1[g];
        }
    }

    float h0[16], h1[16];
#pragma unroll
    for (int l = 0; l < 16; l++) {
        float a0 = b1s[l], a1 = b1s[l];
#pragma unroll
        for (int g = 0; g < 8; g++) {
            float w = W1s[g * 16 + l];
            a0 += t0[g] * w; a1 += t1[g] * w;
        }
        h0[l] = mishf(a0); h1[l] = mishf(a1);
    }

    float a0[16], a1[16];
    const size_t pr = ((size_t)(b * 16) * 512 + n) * 512 + m;   // l stride = 512*512
    float mx0 = -1e30f, mx1 = -1e30f;
#pragma unroll
    for (int l = 0; l < 16; l++) {
        float s0 = b2s[l], s1 = b2s[l];
#pragma unroll
        for (int j = 0; j < 16; j++) {
            float w = W2s[j * 16 + l];
            s0 += h0[j] * w; s1 += h1[j] * w;
        }
        size_t pl = pr + (size_t)l * (512 * 512);
        s0 = s0 * SCALE_ + prior[pl];
        s1 = s1 * SCALE_ + prior[pl + 256];
        a0[l] = s0; a1[l] = s1;
        mx0 = fmaxf(mx0, s0); mx1 = fmaxf(mx1, s1);
    }

    float sum0 = 0.f, sum1 = 0.f;
#pragma unroll
    for (int l = 0; l < 16; l++) {
        a0[l] = __expf(a0[l] - mx0); sum0 += a0[l];
        a1[l] = __expf(a1[l] - mx1); sum1 += a1[l];
    }
    float r0 = __fdividef(1.f, sum0), r1 = __fdividef(1.f, sum1);
#pragma unroll
    for (int l = 0; l < 16; l++) {
        size_t pl = pr + (size_t)l * (512 * 512);
        g_A[pl]       = a0[l] * r0;
        g_A[pl + 256] = a1[l] * r1;
    }
}

// =============================================================================
// K4: AV. For each batch=(b,l): O(512x64) = A_l(512x512) @ V_l(512x64).
// Tile 128x64x16, 256 thr, 8x4/thread.
// =============================================================================
__global__ void __launch_bounds__(256)
k4_av()
{
    __shared__ __align__(16) float As[16][130];
    __shared__ __align__(16) float Bs[16][64];

    const int tid = threadIdx.x;
    const int batch = blockIdx.y;       // 0..255 = b*16+l
    const int rowTile = blockIdx.x;     // 0..3
    const float* Aa = g_A + (size_t)batch * 512 * 512 + (size_t)rowTile * 128 * 512;
    const float* Vv = g_V + (size_t)batch * 512 * 64;

    const int ti = tid >> 4, tj = tid & 15;
    const int i0 = ti * 8, j0 = tj * 4;
    const int akk = tid & 15, arb = tid >> 4;
    const int bkk = tid >> 4, bjc = tid & 15;

    unsigned long long c2[4][4];
#pragma unroll
    for (int p = 0; p < 4; p++)
#pragma unroll
        for (int j = 0; j < 4; j++) c2[p][j] = 0ull;

    for (int k0 = 0; k0 < 512; k0 += 16) {
#pragma unroll
        for (int it = 0; it < 8; it++) {
            int r = arb + 16 * it;
            As[akk][r] = Aa[(size_t)r * 512 + k0 + akk];
        }
        *(float4*)&Bs[bkk][bjc * 4] = *(const float4*)&Vv[(size_t)(k0 + bkk) * 64 + bjc * 4];
        __syncthreads();
#pragma unroll
        for (int kk = 0; kk < 16; kk++) {
            unsigned long long a2[4];
#pragma unroll
            for (int p = 0; p < 4; p++)
                a2[p] = *(const unsigned long long*)&As[kk][i0 + 2 * p];
            float4 bq = *(const float4*)&Bs[kk][j0];
            unsigned long long bb[4] = { pk2(bq.x), pk2(bq.y), pk2(bq.z), pk2(bq.w) };
#pragma unroll
            for (int p = 0; p < 4; p++)
#pragma unroll
                for (int j = 0; j < 4; j++) ffma2(c2[p][j], a2[p], bb[j]);
        }
        __syncthreads();
    }

    const int b = batch >> 4, l = batch & 15;
#pragma unroll
    for (int p = 0; p < 4; p++) {
        float2 rows[4];
#pragma unroll
        for (int j = 0; j < 4; j++) rows[j] = up2(c2[p][j]);
#pragma unroll
        for (int h = 0; h < 2; h++) {
            int n = rowTile * 128 + i0 + 2 * p + h;
            float v[4];
#pragma unroll
            for (int j = 0; j < 4; j++) v[j] = h ? rows[j].y : rows[j].x;
            float* dst = &g_O[(((b * 512 + n) * 16 + l) * 64) + j0];
            *(float4*)dst = make_float4(v[0], v[1], v[2], v[3]);
        }
    }
}

// =============================================================================
// K5: output projection. out(8192x512) = O(8192x1024) @ Wout(1024x512).
// =============================================================================
__global__ void __launch_bounds__(256)
k5_out(const float* __restrict__ Wout, float* __restrict__ out)
{
    __shared__ __align__(16) float As[16][130];
    __shared__ __align__(16) float Bs[16][128];

    const int tid = threadIdx.x;
    const int colTile = blockIdx.x;   // 0..3
    const int rowTile = blockIdx.y;   // 0..63
    const float* Ag = g_O + (size_t)rowTile * 128 * 1024;
    const int colBase = colTile * 128;

    const int ti = tid >> 4, tj = tid & 15;
    const int i0 = ti * 8, j0 = tj * 8;
    const int akk = tid & 15, arb = tid >> 4;

    unsigned long long c2[4][8];
#pragma unroll
    for (int p = 0; p < 4; p++)
#pragma unroll
        for (int j = 0; j < 8; j++) c2[p][j] = 0ull;

    for (int k0 = 0; k0 < 1024; k0 += 16) {
#pragma unroll
        for (int it = 0; it < 8; it++) {
            int r = arb + 16 * it;
            As[akk][r] = Ag[(size_t)r * 1024 + k0 + akk];
        }
#pragma unroll
        for (int it = 0; it < 2; it++) {
            int li = tid + 256 * it;
            int bkk = li >> 5, bjc = li & 31;
            *(float4*)&Bs[bkk][bjc * 4] =
                *(const float4*)&Wout[(size_t)(k0 + bkk) * 512 + colBase + bjc * 4];
        }
        __syncthreads();
#pragma unroll
        for (int kk = 0; kk < 16; kk++) {
            unsigned long long a2[4];
#pragma unroll
            for (int p = 0; p < 4; p++)
                a2[p] = *(const unsigned long long*)&As[kk][i0 + 2 * p];
            float4 b0 = *(const float4*)&Bs[kk][j0];
            float4 b1 = *(const float4*)&Bs[kk][j0 + 4];
            unsigned long long bb[8] = { pk2(b0.x), pk2(b0.y), pk2(b0.z), pk2(b0.w),
                                         pk2(b1.x), pk2(b1.y), pk2(b1.z), pk2(b1.w) };
#pragma unroll
            for (int p = 0; p < 4; p++)
#pragma unroll
                for (int j = 0; j < 8; j++) ffma2(c2[p][j], a2[p], bb[j]);
        }
        __syncthreads();
    }

#pragma unroll
    for (int p = 0; p < 4; p++) {
        float2 rows[8];
#pragma unroll
        for (int j = 0; j < 8; j++) rows[j] = up2(c2[p][j]);
#pragma unroll
        for (int h = 0; h < 2; h++) {
            int r = rowTile * 128 + i0 + 2 * p + h;
            float v[8];
#pragma unroll
            for (int j = 0; j < 8; j++) v[j] = h ? rows[j].y : rows[j].x;
            float* dst = out + (size_t)r * 512 + colBase + j0;
            *(float4*)dst       = make_float4(v[0], v[1], v[2], v[3]);
            *(float4*)(dst + 4) = make_float4(v[4], v[5], v[6], v[7]);
        }
    }
}

// =============================================================================
extern "C" void kernel_launch(void* const* d_in, const int* in_sizes, int n_in,
                              void* d_out, int out_size)
{
    (void)in_sizes; (void)n_in; (void)out_size;
    const float* x     = (const float*)d_in[0];
    const float* prior = (const float*)d_in[1];
    const float* eps   = (const float*)d_in[2];
    const float* Wq    = (const float*)d_in[3];
    const float* Wk    = (const float*)d_in[4];
    const float* Wv    = (const float*)d_in[5];
    const float* bv    = (const float*)d_in[6];
    const float* sigma = (const float*)d_in[7];
    const float* Wp1   = (const float*)d_in[8];
    const float* bp1   = (const float*)d_in[9];
    const float* Wp2   = (const float*)d_in[10];
    const float* bp2   = (const float*)d_in[11];
    const float* Wout  = (const float*)d_in[12];
    float* out = (float*)d_out;

    k1_proj  <<<dim3(16, 64),     256>>>(x, Wq, Wk, Wv, bv);
    k2_scores<<<dim3(4, 4, 128),  256>>>();
    k3_mix   <<<8192,             256>>>(eps, prior, sigma, Wp1, bp1, Wp2, bp2);
    k4_av    <<<dim3(4, 256),     256>>>();
    k5_out   <<<dim3(4, 64),      256>>>(Wout, out);
}

// round 9
// speedup vs baseline: 1.0037x; 1.0037x over previous
#include <cuda_runtime.h>

// ---------------- problem constants ----------------
#define B_ 16
#define N_ 512
#define H_ 512
#define G_ 8
#define L_ 16
#define D_ 64
#define SCALE_ 0.04419417382415922f   // 512^-0.5

// ---------------- device scratch (static: no allocs allowed) ----------------
__device__ float g_Q[B_*G_*N_*D_];          // (b,g,n,d)  16 MB
__device__ float g_K[B_*G_*N_*D_];          // (b,g,m,d)  16 MB
__device__ float g_V[B_*L_*N_*D_];          // (b,l,m,d)  32 MB
__device__ float g_S[B_*G_*N_*N_];          // (b,g,n,m) 128 MB
__device__ float g_A[B_*L_*N_*N_];          // (b,l,n,m) 256 MB
__device__ float g_O[B_*N_*L_*D_];          // (b,n,l,d)  32 MB

// ---------------- f32x2 helpers (FFMA2 only reachable via PTX) --------------
__device__ __forceinline__ unsigned long long pk2(float v) {
    unsigned long long r;
    asm("mov.b64 %0, {%1, %1};" : "=l"(r) : "f"(v));
    return r;
}
__device__ __forceinline__ void ffma2(unsigned long long& d,
                                      unsigned long long a,
                                      unsigned long long b) {
    asm("fma.rn.f32x2 %0, %1, %2, %0;" : "+l"(d) : "l"(a), "l"(b));
}
__device__ __forceinline__ float2 up2(unsigned long long v) {
    float2 f;
    asm("mov.b64 {%0, %1}, %2;" : "=f"(f.x), "=f"(f.y) : "l"(v));
    return f;
}

// mish(x) = x * tanh(softplus(x)) = x * (t^2+2t)/(t^2+2t+2), t = e^x
__device__ __forceinline__ float mishf(float x) {
    float t = __expf(fminf(x, 15.f));   // clamp: for x>15 ratio == 1 to fp32
    float u = t * t + 2.f * t;
    return x * __fdividef(u, u + 2.f);
}

// =============================================================================
// K1: QKV projection.  C(8192 x 2048) = X(8192x512) @ [Wq|Wk|Wv], scatter into
// g_Q (b,g,n,d), g_K (b,g,m,d), g_V (b,l,m,d) (+bv).
// Tile 128x128x16, 256 thr, 8x8/thread, f32x2 accumulators over row pairs.
// =============================================================================
__global__ void __launch_bounds__(256)
k1_proj(const float* __restrict__ x,  const float* __restrict__ Wq,
        const float* __restrict__ Wk, const float* __restrict__ Wv,
        const float* __restrict__ bv)
{
    __shared__ __align__(16) float As[16][130];  // transposed, pad 130 -> conflict-free
    __shared__ __align__(16) float Bs[16][128];

    const int tid = threadIdx.x;
    const int colTile = blockIdx.x;   // 0..15 (16 * 128 = 2048 cols)
    const int rowTile = blockIdx.y;   // 0..63

    const float* Wsrc; int colBase, mode, ldw;
    if (colTile < 4)      { Wsrc = Wq; colBase = colTile * 128;       mode = 0; ldw = 512;  }
    else if (colTile < 8) { Wsrc = Wk; colBase = (colTile - 4) * 128; mode = 1; ldw = 512;  }
    else                  { Wsrc = Wv; colBase = (colTile - 8) * 128; mode = 2; ldw = 1024; }

    const float* Ag = x + (size_t)rowTile * 128 * 512;

    const int ti = tid >> 4, tj = tid & 15;
    const int i0 = ti * 8, j0 = tj * 8;
    const int akk = tid & 15, arb = tid >> 4;

    unsigned long long c2[4][8];
#pragma unroll
    for (int p = 0; p < 4; p++)
#pragma unroll
        for (int j = 0; j < 8; j++) c2[p][j] = 0ull;

    for (int k0 = 0; k0 < 512; k0 += 16) {
#pragma unroll
        for (int it = 0; it < 8; it++) {
            int r = arb + 16 * it;
            As[akk][r] = Ag[(size_t)r * 512 + k0 + akk];
        }
#pragma unroll
        for (int it = 0; it < 2; it++) {
            int li = tid + 256 * it;
            int bkk = li >> 5, bjc = li & 31;
            *(float4*)&Bs[bkk][bjc * 4] =
                *(const float4*)&Wsrc[(size_t)(k0 + bkk) * ldw + colBase + bjc * 4];
        }
        __syncthreads();
#pragma unroll
        for (int kk = 0; kk < 16; kk++) {
            unsigned long long a2[4];
#pragma unroll
            for (int p = 0; p < 4; p++)
                a2[p] = *(const unsigned long long*)&As[kk][i0 + 2 * p];
            float4 b0 = *(const float4*)&Bs[kk][j0];
            float4 b1 = *(const float4*)&Bs[kk][j0 + 4];
            unsigned long long bb[8] = { pk2(b0.x), pk2(b0.y), pk2(b0.z), pk2(b0.w),
                                         pk2(b1.x), pk2(b1.y), pk2(b1.z), pk2(b1.w) };
#pragma unroll
            for (int p = 0; p < 4; p++)
#pragma unroll
                for (int j = 0; j < 8; j++) ffma2(c2[p][j], a2[p], bb[j]);
        }
        __syncthreads();
    }

    const int c = colBase + j0;            // 8 consecutive cols, same head (c%64 multiple of 8)
#pragma unroll
    for (int p = 0; p < 4; p++) {
        float2 rows[8];
#pragma unroll
        for (int j = 0; j < 8; j++) rows[j] = up2(c2[p][j]);
#pragma unroll
        for (int h = 0; h < 2; h++) {
            int i = i0 + 2 * p + h;
            int r = rowTile * 128 + i;
            int b = r >> 9, n = r & 511;
            float v[8];
#pragma unroll
            for (int j = 0; j < 8; j++) v[j] = h ? rows[j].y : rows[j].x;
            if (mode == 2) {
#pragma unroll
                for (int j = 0; j < 8; j++) v[j] += bv[c + j];
                int l = c >> 6, d = c & 63;
                float* dst = &g_V[(((b * 16 + l) * 512 + n) * 64) + d];
                *(float4*)dst       = make_float4(v[0], v[1], v[2], v[3]);
                *(float4*)(dst + 4) = make_float4(v[4], v[5], v[6], v[7]);
            } else {
                int g = c >> 6, d = c & 63;
                float* base = (mode == 0) ? g_Q : g_K;
                float* dst = base + (((b * 8 + g) * 512 + n) * 64) + d;
                *(float4*)dst       = make_float4(v[0], v[1], v[2], v[3]);
                *(float4*)(dst + 4) = make_float4(v[4], v[5], v[6], v[7]);
            }
        }
    }
}

// =============================================================================
// K2: scores. For each z=(b,g): S_z(512x512) = Q_z(512x64) @ K_z(512x64)^T.
// NT GEMM: both operands transpose-loaded into smem (pad 130).
// =============================================================================
__global__ void __launch_bounds__(256)
k2_scores()
{
    __shared__ __align__(16) float As[16][130];
    __shared__ __align__(16) float Bs[16][130];

    const int tid = threadIdx.x;
    const int z = blockIdx.z;                         // b*8+g
    const float* Qg = g_Q + (size_t)z * 512 * 64;
    const float* Kg = g_K + (size_t)z * 512 * 64;
    const int rowTile = blockIdx.y, colTile = blockIdx.x;   // each 0..3

    const int ti = tid >> 4, tj = tid & 15;
    const int i0 = ti * 8, j0 = tj * 8;
    const int lkk = tid & 15, lrb = tid >> 4;

    unsigned long long c2[4][8];
#pragma unroll
    for (int p = 0; p < 4; p++)
#pragma unroll
        for (int j = 0; j < 8; j++) c2[p][j] = 0ull;

    for (int k0 = 0; k0 < 64; k0 += 16) {
#pragma unroll
        for (int it = 0; it < 8; it++) {
            int r = lrb + 16 * it;
            As[lkk][r] = Qg[(size_t)(rowTile * 128 + r) * 64 + k0 + lkk];
            Bs[lkk][r] = Kg[(size_t)(colTile * 128 + r) * 64 + k0 + lkk];
        }
        __syncthreads();
#pragma unroll
        for (int kk = 0; kk < 16; kk++) {
            unsigned long long a2[4];
#pragma unroll
            for (int p = 0; p < 4; p++)
                a2[p] = *(const unsigned long long*)&As[kk][i0 + 2 * p];
            unsigned long long bb[8];
#pragma unroll
            for (int q = 0; q < 4; q++) {
                float2 bq = *(const float2*)&Bs[kk][j0 + 2 * q];
                bb[2 * q]     = pk2(bq.x);
                bb[2 * q + 1] = pk2(bq.y);
            }
#pragma unroll
            for (int p = 0; p < 4; p++)
#pragma unroll
                for (int j = 0; j < 8; j++) ffma2(c2[p][j], a2[p], bb[j]);
        }
        __syncthreads();
    }

    float* Sb = g_S + (size_t)z * 512 * 512;
#pragma unroll
    for (int p = 0; p < 4; p++) {
        float2 rows[8];
#pragma unroll
        for (int j = 0; j < 8; j++) rows[j] = up2(c2[p][j]);
#pragma unroll
        for (int h = 0; h < 2; h++) {
            int n = rowTile * 128 + i0 + 2 * p + h;
            float v[8];
#pragma unroll
            for (int j = 0; j < 8; j++) v[j] = h ? rows[j].y : rows[j].x;
            float* dst = Sb + (size_t)n * 512 + colTile * 128 + j0;
            *(float4*)dst       = make_float4(v[0], v[1], v[2], v[3]);
            *(float4*)(dst + 4) = make_float4(v[4], v[5], v[6], v[7]);
        }
    }
}

// =============================================================================
// K3: pointwise head-mix. a8 = S + sigma^2*eps; a16 = mish(a8@Wp1+bp1)@Wp2+bp2;
// a16 = a16*SCALE + prior(b,l,n,m); softmax over l (16); write A (b,l,n,m).
// 2 points per thread (m and m+256) to amortize weight LDS.
// =============================================================================
__global__ void __launch_bounds__(256)
k3_mix(const float* __restrict__ eps,  const float* __restrict__ prior,
       const float* __restrict__ sigma, const float* __restrict__ Wp1,
       const float* __restrict__ bp1,   const float* __restrict__ Wp2,
       const float* __restrict__ bp2)
{
    __shared__ float W1s[128];
    __shared__ float W2s[256];
    __shared__ float b1s[16], b2s[16], sg2[8];

    const int tid = threadIdx.x;
    if (tid < 128) W1s[tid] = Wp1[tid];
    W2s[tid] = Wp2[tid];
    if (tid < 16) { b1s[tid] = bp1[tid]; b2s[tid] = bp2[tid]; }
    if (tid < 8)  { float s = sigma[tid]; sg2[tid] = s * s; }
    __syncthreads();

    const int gidx = blockIdx.x * 256 + tid;   // grid 8192 -> 2.097M threads
    const int m = gidx & 255;
    const int n = (gidx >> 8) & 511;
    const int b = gidx >> 17;

    const size_t p0 = ((size_t)(b * 512 + n)) * 512 + m;   // (b,n,m) flat

    float t0[8], t1[8];
    {
        float e0[8], e1[8];
        const float4* ep0 = (const float4*)(eps + p0 * 8);
        const float4* ep1 = (const float4*)(eps + (p0 + 256) * 8);
        *(float4*)&e0[0] = ep0[0]; *(float4*)&e0[4] = ep0[1];
        *(float4*)&e1[0] = ep1[0]; *(float4*)&e1[4] = ep1[1];
#pragma unroll
        for (int g = 0; g < 8; g++) {
            size_t si = ((size_t)(b * 8 + g) * 512 + n) * 512 + m;
            t0[g] = g_S[si]       + sg2[g] * e0[g];
            t1[g] = g_S[si + 256] + sg2[g] * e1[g];
        }
    }

    float h0[16], h1[16];
#pragma unroll
    for (int l = 0; l < 16; l++) {
        float a0 = b1s[l], a1 = b1s[l];
#pragma unroll
        for (int g = 0; g < 8; g++) {
            float w = W1s[g * 16 + l];
            a0 += t0[g] * w; a1 += t1[g] * w;
        }
        h0[l] = mishf(a0); h1[l] = mishf(a1);
    }

    float a0[16], a1[16];
    const size_t pr = ((size_t)(b * 16) * 512 + n) * 512 + m;   // l stride = 512*512
    float mx0 = -1e30f, mx1 = -1e30f;
#pragma unroll
    for (int l = 0; l < 16; l++) {
        float s0 = b2s[l], s1 = b2s[l];
#pragma unroll
        for (int j = 0; j < 16; j++) {
            float w = W2s[j * 16 + l];
            s0 += h0[j] * w; s1 += h1[j] * w;
        }
        size_t pl = pr + (size_t)l * (512 * 512);
        s0 = s0 * SCALE_ + prior[pl];
        s1 = s1 * SCALE_ + prior[pl + 256];
        a0[l] = s0; a1[l] = s1;
        mx0 = fmaxf(mx0, s0); mx1 = fmaxf(mx1, s1);
    }

    float sum0 = 0.f, sum1 = 0.f;
#pragma unroll
    for (int l = 0; l < 16; l++) {
        a0[l] = __expf(a0[l] - mx0); sum0 += a0[l];
        a1[l] = __expf(a1[l] - mx1); sum1 += a1[l];
    }
    float r0 = __fdividef(1.f, sum0), r1 = __fdividef(1.f, sum1);
#pragma unroll
    for (int l = 0; l < 16; l++) {
        size_t pl = pr + (size_t)l * (512 * 512);
        g_A[pl]       = a0[l] * r0;
        g_A[pl + 256] = a1[l] * r1;
    }
}

// =============================================================================
// K4: AV. For each batch=(b,l): O(512x64) = A_l(512x512) @ V_l(512x64).
// Tile 128x64x16, 256 thr, 8x4/thread.
// =============================================================================
__global__ void __launch_bounds__(256)
k4_av()
{
    __shared__ __align__(16) float As[16][130];
    __shared__ __align__(16) float Bs[16][64];

    const int tid = threadIdx.x;
    const int batch = blockIdx.y;       // 0..255 = b*16+l
    const int rowTile = blockIdx.x;     // 0..3
    const float* Aa = g_A + (size_t)batch * 512 * 512 + (size_t)rowTile * 128 * 512;
    const float* Vv = g_V + (size_t)batch * 512 * 64;

    const int ti = tid >> 4, tj = tid & 15;
    const int i0 = ti * 8, j0 = tj * 4;
    const int akk = tid & 15, arb = tid >> 4;
    const int bkk = tid >> 4, bjc = tid & 15;

    unsigned long long c2[4][4];
#pragma unroll
    for (int p = 0; p < 4; p++)
#pragma unroll
        for (int j = 0; j < 4; j++) c2[p][j] = 0ull;

    for (int k0 = 0; k0 < 512; k0 += 16) {
#pragma unroll
        for (int it = 0; it < 8; it++) {
            int r = arb + 16 * it;
            As[akk][r] = Aa[(size_t)r * 512 + k0 + akk];
        }
        *(float4*)&Bs[bkk][bjc * 4] = *(const float4*)&Vv[(size_t)(k0 + bkk) * 64 + bjc * 4];
        __syncthreads();
#pragma unroll
        for (int kk = 0; kk < 16; kk++) {
            unsigned long long a2[4];
#pragma unroll
            for (int p = 0; p < 4; p++)
                a2[p] = *(const unsigned long long*)&As[kk][i0 + 2 * p];
            float4 bq = *(const float4*)&Bs[kk][j0];
            unsigned long long bb[4] = { pk2(bq.x), pk2(bq.y), pk2(bq.z), pk2(bq.w) };
#pragma unroll
            for (int p = 0; p < 4; p++)
#pragma unroll
                for (int j = 0; j < 4; j++) ffma2(c2[p][j], a2[p], bb[j]);
        }
        __syncthreads();
    }

    const int b = batch >> 4, l = batch & 15;
#pragma unroll
    for (int p = 0; p < 4; p++) {
        float2 rows[4];
#pragma unroll
        for (int j = 0; j < 4; j++) rows[j] = up2(c2[p][j]);
#pragma unroll
        for (int h = 0; h < 2; h++) {
            int n = rowTile * 128 + i0 + 2 * p + h;
            float v[4];
#pragma unroll
            for (int j = 0; j < 4; j++) v[j] = h ? rows[j].y : rows[j].x;
            float* dst = &g_O[(((b * 512 + n) * 16 + l) * 64) + j0];
            *(float4*)dst = make_float4(v[0], v[1], v[2], v[3]);
        }
    }
}

// =============================================================================
// K5: output projection. out(8192x512) = O(8192x1024) @ Wout(1024x512).
// =============================================================================
__global__ void __launch_bounds__(256)
k5_out(const float* __restrict__ Wout, float* __restrict__ out)
{
    __shared__ __align__(16) float As[16][130];
    __shared__ __align__(16) float Bs[16][128];

    const int tid = threadIdx.x;
    const int colTile = blockIdx.x;   // 0..3
    const int rowTile = blockIdx.y;   // 0..63
    const float* Ag = g_O + (size_t)rowTile * 128 * 1024;
    const int colBase = colTile * 128;

    const int ti = tid >> 4, tj = tid & 15;
    const int i0 = ti * 8, j0 = tj * 8;
    const int akk = tid & 15, arb = tid >> 4;

    unsigned long long c2[4][8];
#pragma unroll
    for (int p = 0; p < 4; p++)
#pragma unroll
        for (int j = 0; j < 8; j++) c2[p][j] = 0ull;

    for (int k0 = 0; k0 < 1024; k0 += 16) {
#pragma unroll
        for (int it = 0; it < 8; it++) {
            int r = arb + 16 * it;
            As[akk][r] = Ag[(size_t)r * 1024 + k0 + akk];
        }
#pragma unroll
        for (int it = 0; it < 2; it++) {
            int li = tid + 256 * it;
            int bkk = li >> 5, bjc = li & 31;
            *(float4*)&Bs[bkk][bjc * 4] =
                *(const float4*)&Wout[(size_t)(k0 + bkk) * 512 + colBase + bjc * 4];
        }
        __syncthreads();
#pragma unroll
        for (int kk = 0; kk < 16; kk++) {
            unsigned long long a2[4];
#pragma unroll
            for (int p = 0; p < 4; p++)
                a2[p] = *(const unsigned long long*)&As[kk][i0 + 2 * p];
            float4 b0 = *(const float4*)&Bs[kk][j0];
            float4 b1 = *(const float4*)&Bs[kk][j0 + 4];
            unsigned long long bb[8] = { pk2(b0.x), pk2(b0.y), pk2(b0.z), pk2(b0.w),
                                         pk2(b1.x), pk2(b1.y), pk2(b1.z), pk2(b1.w) };
#pragma unroll
            for (int p = 0; p < 4; p++)
#pragma unroll
                for (int j = 0; j < 8; j++) ffma2(c2[p][j], a2[p], bb[j]);
        }
        __syncthreads();
    }

#pragma unroll
    for (int p = 0; p < 4; p++) {
        float2 rows[8];
#pragma unroll
        for (int j = 0; j < 8; j++) rows[j] = up2(c2[p][j]);
#pragma unroll
        for (int h = 0; h < 2; h++) {
            int r = rowTile * 128 + i0 + 2 * p + h;
            float v[8];
#pragma unroll
            for (int j = 0; j < 8; j++) v[j] = h ? rows[j].y : rows[j].x;
            float* dst = out + (size_t)r * 512 + colBase + j0;
            *(float4*)dst       = make_float4(v[0], v[1], v[2], v[3]);
            *(float4*)(dst + 4) = make_float4(v[4], v[5], v[6], v[7]);
        }
    }
}

// =============================================================================
extern "C" void kernel_launch(void* const* d_in, const int* in_sizes, int n_in,
                              void* d_out, int out_size)
{
    (void)in_sizes; (void)n_in; (void)out_size;
    const float* x     = (const float*)d_in[0];
    const float* prior = (const float*)d_in[1];
    const float* eps   = (const float*)d_in[2];
    const float* Wq    = (const float*)d_in[3];
    const float* Wk    = (const float*)d_in[4];
    const float* Wv    = (const float*)d_in[5];
    const float* bv    = (const float*)d_in[6];
    const float* sigma = (const float*)d_in[7];
    const float* Wp1   = (const float*)d_in[8];
    const float* bp1   = (const float*)d_in[9];
    const float* Wp2   = (const float*)d_in[10];
    const float* bp2   = (const float*)d_in[11];
    const float* Wout  = (const float*)d_in[12];
    float* out = (float*)d_out;

    k1_proj  <<<dim3(16, 64),     256>>>(x, Wq, Wk, Wv, bv);
    k2_scores<<<dim3(4, 4, 128),  256>>>();
    k3_mix   <<<8192,             256>>>(eps, prior, sigma, Wp1, bp1, Wp2, bp2);
    k4_av    <<<dim3(4, 256),     256>>>();
    k5_out   <<<dim3(4, 64),      256>>>(Wout, out);
}